// round 11
// baseline (speedup 1.0000x reference)
#include <cuda_runtime.h>

// NECTAR binning — 128x4 warp bands + CTA-internal vertical halo exchange.
// CTA = 4 warps = 128x16 tile; inter-warp boundary rows shared via smem W3
// instead of redundant reloads. logits [16,4,512,512] f32 -> out same shape.

#define H_DIM 512
#define W_DIM 512
#define HW    (H_DIM * W_DIM)
#define NTH   128

__device__ __forceinline__ unsigned int argmax_w(float l0, float l1, float l2, float l3,
                                                 float& m) {
    m = l0; unsigned int w = 1u;
    if (l1 > m) { m = l1; w = 1u << 8;  }
    if (l2 > m) { m = l2; w = 1u << 16; }
    if (l3 > m) { m = l3; w = 1u << 24; }
    return w;
}

__device__ __forceinline__ void row_cw(const float* __restrict__ pr, unsigned int cw[4]) {
    const float4 A  = *(const float4*)(pr);
    const float4 Bv = *(const float4*)(pr + HW);
    const float4 Cv = *(const float4*)(pr + 2 * HW);
    const float4 Dv = *(const float4*)(pr + 3 * HW);
    const float p0[4] = {A.x, A.y, A.z, A.w};
    const float p1[4] = {Bv.x, Bv.y, Bv.z, Bv.w};
    const float p2[4] = {Cv.x, Cv.y, Cv.z, Cv.w};
    const float p3[4] = {Dv.x, Dv.y, Dv.z, Dv.w};
    float m;
    #pragma unroll
    for (int j = 0; j < 4; j++)
        cw[j] = argmax_w(p0[j], p1[j], p2[j], p3[j], m);
}

__device__ __forceinline__ void row_full4(const float* __restrict__ pr,
                                          unsigned int cw[4], unsigned int binw[4]) {
    const float4 A  = *(const float4*)(pr);
    const float4 Bv = *(const float4*)(pr + HW);
    const float4 Cv = *(const float4*)(pr + 2 * HW);
    const float4 Dv = *(const float4*)(pr + 3 * HW);
    const float p0[4] = {A.x, A.y, A.z, A.w};
    const float p1[4] = {Bv.x, Bv.y, Bv.z, Bv.w};
    const float p2[4] = {Cv.x, Cv.y, Cv.z, Cv.w};
    const float p3[4] = {Dv.x, Dv.y, Dv.z, Dv.w};
    const float bw = 1.0f / 15.0f;

    #pragma unroll
    for (int j = 0; j < 4; j++) {
        const float l0 = p0[j], l1 = p1[j], l2 = p2[j], l3 = p3[j];
        float m;
        cw[j] = argmax_w(l0, l1, l2, l3, m);

        const float e0 = __expf(l0);
        const float e1 = __expf(l1);
        const float e2 = __expf(l2);
        const float e3 = __expf(l3);
        const float s  = e0 + e1 + e2 + e3;
        const float tt = __fdividef(15.0f, s);
        const float u0 = e0 * tt, u1 = e1 * tt, u2 = e2 * tt, u3 = e3 * tt;
        int b0 = (int)u0, b1 = (int)u1, b2 = (int)u2, b3 = (int)u3;

        const float g = 1e-4f;   // fast-path |u| error bound ~2.3e-5 -> 4x margin
        const float d0 = fminf(fabsf(u0 - rintf(u0)), fabsf(u1 - rintf(u1)));
        const float d1 = fminf(fabsf(u2 - rintf(u2)), fabsf(u3 - rintf(u3)));
        if (fminf(d0, d1) < g) {
            // exact path: bit-validated reference formula
            const float a0 = expf(l0 - m);
            const float a1 = expf(l1 - m);
            const float a2 = expf(l2 - m);
            const float a3 = expf(l3 - m);
            const float as = a0 + a1 + a2 + a3;
            const float at = (1.0f / as) / bw;
            b0 = (int)(a0 * at);
            b1 = (int)(a1 * at);
            b2 = (int)(a2 * at);
            b3 = (int)(a3 * at);
        }
        b0 = b0 > 14 ? 14 : b0;
        b1 = b1 > 14 ? 14 : b1;
        b2 = b2 > 14 ? 14 : b2;
        b3 = b3 > 14 ? 14 : b3;
        const unsigned int t0 = __byte_perm((unsigned)b0, (unsigned)b1, 0x0040);
        const unsigned int t1 = __byte_perm((unsigned)b2, (unsigned)b3, 0x0040);
        binw[j] = __byte_perm(t0, t1, 0x5410);
    }
}

__device__ __forceinline__ unsigned int halo_w(const float* __restrict__ pb,
                                               int gy, bool doit, int dx) {
    if (!doit) return 0u;
    const float* hp = pb + (unsigned)gy * W_DIM + dx;
    const float l0 = __ldg(hp);
    const float l1 = __ldg(hp + HW);
    const float l2 = __ldg(hp + 2 * HW);
    const float l3 = __ldg(hp + 3 * HW);
    float m;
    return argmax_w(l0, l1, l2, l3, m);
}

__device__ __forceinline__ void hwin(const unsigned int cw[4], unsigned int hw_,
                                     int lane, unsigned int W3[4]) {
    unsigned int prev = __shfl_up_sync(0xffffffffu, cw[3], 1);
    if (lane == 0)  prev = hw_;
    unsigned int nxt  = __shfl_down_sync(0xffffffffu, cw[0], 1);
    if (lane == 31) nxt = hw_;
    const unsigned int p01 = cw[0] + cw[1];
    const unsigned int p23 = cw[2] + cw[3];
    W3[0] = prev  + p01;
    W3[1] = p01   + cw[2];
    W3[2] = cw[1] + p23;
    W3[3] = p23   + nxt;
}

__device__ __forceinline__ void emit_row(float* __restrict__ po,
                                         const unsigned int S[4], const unsigned int W3[4],
                                         const unsigned int binsp[4],
                                         const float* __restrict__ s_vf) {
    float o0[4], o1[4], o2[4], o3[4];
    #pragma unroll
    for (int j = 0; j < 4; j++) {
        const unsigned int acc = S[j] + W3[j];
        const unsigned int idx = acc * 15u + binsp[j];   // per-byte 15*cnt+bin <= 134
        const float f0 = s_vf[        ( idx         & 0xFFu)];
        const float f1 = s_vf[135u + ((idx >> 8)    & 0xFFu)];
        const float f2 = s_vf[270u + ((idx >> 16)   & 0xFFu)];
        const float f3 = s_vf[405u + ( idx >> 24          )];
        float s = f0 + f1 + f2 + f3;
        s = (s == 0.0f) ? 1.0f : s;
        const float inv = __fdividef(1.0f, s);
        o0[j] = f0 * inv; o1[j] = f1 * inv; o2[j] = f2 * inv; o3[j] = f3 * inv;
    }
    __stcs((float4*)(po),          make_float4(o0[0], o0[1], o0[2], o0[3]));
    __stcs((float4*)(po + HW),     make_float4(o1[0], o1[1], o1[2], o1[3]));
    __stcs((float4*)(po + 2 * HW), make_float4(o2[0], o2[1], o2[2], o2[3]));
    __stcs((float4*)(po + 3 * HW), make_float4(o3[0], o3[1], o3[2], o3[3]));
}

__global__ __launch_bounds__(NTH, 7)
void nectar_binning_kernel(const float* __restrict__ logits,
                           const float* __restrict__ val_freqs,
                           float* __restrict__ out)
{
    __shared__ float s_vf[540];
    __shared__ uint4 s_w3[4][2][32];     // [warp][first/last row][lane] -> W3 words

    const int tid  = threadIdx.x;
    const int lane = tid & 31;
    const int wrp  = tid >> 5;

    for (int i = tid; i < 540; i += NTH) s_vf[i] = val_freqs[i];

    const int x0     = blockIdx.x * 128;
    const int cta_y0 = blockIdx.y * 16;
    const int ybase  = cta_y0 + wrp * 4;
    const unsigned int boff = blockIdx.z * 4u * HW;

    const float* pb = logits + boff + (unsigned)x0 + 4u * (unsigned)lane;
    float*       ob = out    + boff + (unsigned)x0 + 4u * (unsigned)lane;

    const bool edgeLane = (lane == 0) | (lane == 31);
    const bool haloOk   = edgeLane & ((lane == 0) ? (x0 > 0) : (x0 + 128 < W_DIM));
    const int  haloDx   = (lane == 0) ? -1 : 4;

    // ================= Phase 1: own band's first (0) and last (3) rows =====
    unsigned int cwA[4], binA[4], W3A[4];
    unsigned int cwB[4], binB[4], W3B[4];
    row_full4(pb + (unsigned)ybase * W_DIM, cwA, binA);
    row_full4(pb + (unsigned)(ybase + 3) * W_DIM, cwB, binB);
    {
        const unsigned int hwA = halo_w(pb, ybase,     haloOk, haloDx);
        const unsigned int hwB = halo_w(pb, ybase + 3, haloOk, haloDx);
        hwin(cwA, hwA, lane, W3A);
        hwin(cwB, hwB, lane, W3B);
    }
    s_w3[wrp][0][lane] = make_uint4(W3A[0], W3A[1], W3A[2], W3A[3]);
    s_w3[wrp][1][lane] = make_uint4(W3B[0], W3B[1], W3B[2], W3B[3]);
    __syncthreads();

    // ================= Phase 2: stream band rows 0..3 ======================
    // W3 of row -1: neighbor warp's last row, or exterior load for warp 0.
    unsigned int W3m[4];
    if (wrp > 0) {
        const uint4 t = s_w3[wrp - 1][1][lane];
        W3m[0] = t.x; W3m[1] = t.y; W3m[2] = t.z; W3m[3] = t.w;
    } else {
        const int gy = ybase - 1;
        if (gy >= 0) {
            unsigned int cw[4];
            row_cw(pb + (unsigned)gy * W_DIM, cw);
            const unsigned int hw_ = halo_w(pb, gy, haloOk, haloDx);
            hwin(cw, hw_, lane, W3m);
        } else {
            W3m[0] = W3m[1] = W3m[2] = W3m[3] = 0u;
        }
    }

    unsigned int S[4], W3p[4], binsp[4];
    #pragma unroll
    for (int j = 0; j < 4; j++) {
        S[j]     = W3m[j] + (W3A[j] - cwA[j]);
        W3p[j]   = W3A[j];
        binsp[j] = binA[j];
    }

    // rows 1,2: fresh loads; emit rows 0,1
    #pragma unroll
    for (int r = 1; r <= 2; ++r) {
        const int gy = ybase + r;
        unsigned int cw[4], binw[4], W3[4];
        row_full4(pb + (unsigned)gy * W_DIM, cw, binw);
        const unsigned int hw_ = halo_w(pb, gy, haloOk, haloDx);
        hwin(cw, hw_, lane, W3);
        emit_row(ob + (unsigned)(gy - 1) * W_DIM, S, W3, binsp, s_vf);
        #pragma unroll
        for (int j = 0; j < 4; j++) {
            S[j]     = W3p[j] + (W3[j] - cw[j]);
            W3p[j]   = W3[j];
            binsp[j] = binw[j];
        }
    }

    // row 3: reuse phase-1 result; emit row 2
    emit_row(ob + (unsigned)(ybase + 2) * W_DIM, S, W3B, binsp, s_vf);
    #pragma unroll
    for (int j = 0; j < 4; j++) {
        S[j]     = W3p[j] + (W3B[j] - cwB[j]);
        binsp[j] = binB[j];
    }

    // row 4 (below band): neighbor warp's first row, or exterior for warp 3
    unsigned int W3b[4];
    if (wrp < 3) {
        const uint4 t = s_w3[wrp + 1][0][lane];
        W3b[0] = t.x; W3b[1] = t.y; W3b[2] = t.z; W3b[3] = t.w;
    } else {
        const int gy = ybase + 4;
        if (gy < H_DIM) {
            unsigned int cw[4];
            row_cw(pb + (unsigned)gy * W_DIM, cw);
            const unsigned int hw_ = halo_w(pb, gy, haloOk, haloDx);
            hwin(cw, hw_, lane, W3b);
        } else {
            W3b[0] = W3b[1] = W3b[2] = W3b[3] = 0u;
        }
    }
    emit_row(ob + (unsigned)(ybase + 3) * W_DIM, S, W3b, binsp, s_vf);
}

extern "C" void kernel_launch(void* const* d_in, const int* in_sizes, int n_in,
                              void* d_out, int out_size)
{
    const float* logits    = (const float*)d_in[0];
    const float* val_freqs = (const float*)d_in[1];
    float*       out       = (float*)d_out;

    const int B = in_sizes[0] / (4 * HW);        // 16

    dim3 grid(W_DIM / 128, H_DIM / 16, B);       // 4 x 32 x 16 = 2048 CTAs
    nectar_binning_kernel<<<grid, NTH>>>(logits, val_freqs, out);
}